// round 5
// baseline (speedup 1.0000x reference)
#include <cuda_runtime.h>
#include <cuda_fp16.h>
#include <math.h>

#define HID    1024
#define GATES  4096
#define LATENT 2048
#define SEQ    16
#define WHH_ELEMS (GATES * HID)   // 4M per layer

// ---------------- device scratch (no allocation allowed) ----------------
__device__ float  g_xg[SEQ * GATES];    // pre-activation gates, current layer
__device__ float  g_h1[SEQ * HID];      // layer-0 hidden outputs (per-step rows)
__device__ float  g_c[HID];             // cell state (reset via first-step flag)
__device__ __half g_whh0_h[WHH_ELEMS];  // fp16 copy of w_hh0
__device__ __half g_whh1_h[WHH_ELEMS];  // fp16 copy of w_hh1

__device__ __forceinline__ float sigmoidf_(float x) {
    return 1.0f / (1.0f + __expf(-x));
}

// ---------------- fp32 -> fp16 weight conversion (both layers, one pass) ---
__global__ void __launch_bounds__(256, 1)
convert_whh_kernel(const float* __restrict__ w0, const float* __restrict__ w1) {
    const size_t per = WHH_ELEMS / 8;                    // 512K chunks of 8
    size_t i = (size_t)blockIdx.x * 256 + threadIdx.x;   // grid covers 2*per
    const float4* src;
    __half* dst;
    size_t k;
    if (i < per) { src = (const float4*)w0; dst = g_whh0_h; k = i; }
    else         { src = (const float4*)w1; dst = g_whh1_h; k = i - per; }
    float4 a = src[2 * k], b = src[2 * k + 1];
    __half2 h0 = __floats2half2_rn(a.x, a.y);
    __half2 h1 = __floats2half2_rn(a.z, a.w);
    __half2 h2 = __floats2half2_rn(b.x, b.y);
    __half2 h3 = __floats2half2_rn(b.z, b.w);
    uint4 o;
    o.x = *(unsigned*)&h0; o.y = *(unsigned*)&h1;
    o.z = *(unsigned*)&h2; o.w = *(unsigned*)&h3;
    ((uint4*)dst)[k] = o;
}

// ---------------- batched input GEMM kernel (unchanged, fp32) --------------
// out[t][row] = inp[t] . W[row] + b1[row] + b2[row]
template <int D>
__global__ void __launch_bounds__(256, 1)
gate_gemm_kernel(const float* __restrict__ W,
                 const float* __restrict__ inp,
                 const float* __restrict__ b1,
                 const float* __restrict__ b2,
                 float* __restrict__ out) {
    extern __shared__ float smem[];
    const int tid  = threadIdx.x;
    const int lane = tid & 31;
    const int warp = tid >> 5;
    const int NF4  = D / 4;

    for (int i = tid; i < SEQ * D; i += 256) smem[i] = inp[i];
    __syncthreads();
    const float4* xs4 = (const float4*)smem;

    const int row = (blockIdx.x * 8 + warp) * 4;

    float acc[4][SEQ];
#pragma unroll
    for (int r = 0; r < 4; r++)
#pragma unroll
        for (int t = 0; t < SEQ; t++) acc[r][t] = 0.0f;

    const float4* w0 = (const float4*)(W + (size_t)(row + 0) * D);
    const float4* w1 = (const float4*)(W + (size_t)(row + 1) * D);
    const float4* w2 = (const float4*)(W + (size_t)(row + 2) * D);
    const float4* w3 = (const float4*)(W + (size_t)(row + 3) * D);

    for (int ci = lane; ci < NF4; ci += 32) {
        float4 a0 = w0[ci], a1 = w1[ci], a2 = w2[ci], a3 = w3[ci];
#pragma unroll
        for (int t = 0; t < SEQ; t++) {
            float4 xv = xs4[t * NF4 + ci];
            acc[0][t] += a0.x * xv.x + a0.y * xv.y + a0.z * xv.z + a0.w * xv.w;
            acc[1][t] += a1.x * xv.x + a1.y * xv.y + a1.z * xv.z + a1.w * xv.w;
            acc[2][t] += a2.x * xv.x + a2.y * xv.y + a2.z * xv.z + a2.w * xv.w;
            acc[3][t] += a3.x * xv.x + a3.y * xv.y + a3.z * xv.z + a3.w * xv.w;
        }
    }
#pragma unroll
    for (int r = 0; r < 4; r++) {
#pragma unroll
        for (int t = 0; t < SEQ; t++) {
            float s = acc[r][t];
#pragma unroll
            for (int off = 16; off; off >>= 1)
                s += __shfl_xor_sync(0xffffffffu, s, off);
            if (lane == 0)
                out[t * GATES + row + r] = s + b1[row + r] + b2[row + r];
        }
    }
}

// ---------------- one LSTM timestep (fp16 weights, fp32 math) --------------
// grid = 256 CTAs x 128 thr. Warp (blockIdx*4+warp) owns hidden unit j.
// h_prev staged once per CTA in SMEM, then held in 32 registers per lane and
// reused across all 4 gate rows. 16 independent LDG.128 of fp16 weights per
// lane -> high MLP. Accumulation fp32; shuffles reduce; lane 0 pointwise.
__global__ void __launch_bounds__(128, 4)
lstm_step_kernel(const __half* __restrict__ whh,
                 const float* __restrict__ xg_t,
                 const float* __restrict__ h_prev,   // ignored if first
                 float* __restrict__ c_state,
                 float* __restrict__ h_out,
                 float* __restrict__ last_out,       // null unless t == SEQ-1
                 int first) {
    __shared__ float hs[HID];
    const int lane = threadIdx.x & 31;
    const int warp = threadIdx.x >> 5;
    const int j    = blockIdx.x * 4 + warp;

    float dot[4] = {0.f, 0.f, 0.f, 0.f};
    if (!first) {
        // stage h_{t-1} (4 KB) once per CTA
        {
            const float4* hp4 = (const float4*)h_prev;
            float4* hs4 = (float4*)hs;
            for (int i = threadIdx.x; i < HID / 4; i += 128) hs4[i] = hp4[i];
        }
        __syncthreads();

        // lane covers 8-element chunks lane+32q (q<4) of every gate row
        float hreg[32];
#pragma unroll
        for (int q = 0; q < 4; q++) {
            const float4* p = (const float4*)(hs + 8 * (lane + 32 * q));
            float4 a = p[0], b = p[1];
            hreg[q * 8 + 0] = a.x; hreg[q * 8 + 1] = a.y;
            hreg[q * 8 + 2] = a.z; hreg[q * 8 + 3] = a.w;
            hreg[q * 8 + 4] = b.x; hreg[q * 8 + 5] = b.y;
            hreg[q * 8 + 6] = b.z; hreg[q * 8 + 7] = b.w;
        }

#pragma unroll
        for (int g = 0; g < 4; g++) {
            const uint4* wr = (const uint4*)(whh + (size_t)(g * HID + j) * HID);
            float s = 0.0f;
#pragma unroll
            for (int q = 0; q < 4; q++) {
                uint4 w = wr[lane + 32 * q];
                const __half2* hw = (const __half2*)&w;
#pragma unroll
                for (int i = 0; i < 4; i++) {
                    float2 f = __half22float2(hw[i]);
                    s += f.x * hreg[q * 8 + 2 * i] + f.y * hreg[q * 8 + 2 * i + 1];
                }
            }
            dot[g] = s;
        }
#pragma unroll
        for (int g = 0; g < 4; g++)
#pragma unroll
            for (int off = 16; off; off >>= 1)
                dot[g] += __shfl_xor_sync(0xffffffffu, dot[g], off);
    }

    if (lane == 0) {
        float gi = xg_t[0 * HID + j] + dot[0];
        float gf = xg_t[1 * HID + j] + dot[1];
        float gg = xg_t[2 * HID + j] + dot[2];
        float go = xg_t[3 * HID + j] + dot[3];
        float iv = sigmoidf_(gi);
        float fv = sigmoidf_(gf);
        float gv = tanhf(gg);
        float ov = sigmoidf_(go);
        float cprev = first ? 0.0f : c_state[j];
        float cn = fv * cprev + iv * gv;
        c_state[j] = cn;
        float hval = ov * tanhf(cn);
        h_out[j] = hval;
        if (last_out) last_out[j] = hval;
    }
}

// ---------------- host-side launch sequence (graph-capturable) -------------
extern "C" void kernel_launch(void* const* d_in, const int* in_sizes, int n_in,
                              void* d_out, int out_size) {
    const float* x     = (const float*)d_in[0];
    const float* w_ih0 = (const float*)d_in[1];
    const float* w_hh0 = (const float*)d_in[2];
    const float* b_ih0 = (const float*)d_in[3];
    const float* b_hh0 = (const float*)d_in[4];
    const float* w_ih1 = (const float*)d_in[5];
    const float* w_hh1 = (const float*)d_in[6];
    const float* b_ih1 = (const float*)d_in[7];
    const float* b_hh1 = (const float*)d_in[8];
    float* out = (float*)d_out;   // [0:HID) = last_output, [HID:) = h2 rows

    float *xg, *h1, *c;
    __half *whh0h, *whh1h;
    cudaGetSymbolAddress((void**)&xg, g_xg);
    cudaGetSymbolAddress((void**)&h1, g_h1);
    cudaGetSymbolAddress((void**)&c,  g_c);
    cudaGetSymbolAddress((void**)&whh0h, g_whh0_h);
    cudaGetSymbolAddress((void**)&whh1h, g_whh1_h);

    cudaFuncSetAttribute(gate_gemm_kernel<LATENT>,
                         cudaFuncAttributeMaxDynamicSharedMemorySize,
                         SEQ * LATENT * 4);
    cudaFuncSetAttribute(gate_gemm_kernel<HID>,
                         cudaFuncAttributeMaxDynamicSharedMemorySize,
                         SEQ * HID * 4);

    // weight conversion (both layers, one pass; feeds all 32 step kernels)
    convert_whh_kernel<<<2 * (WHH_ELEMS / 8) / 256, 256>>>(w_hh0, w_hh1);

    // Layer 0
    gate_gemm_kernel<LATENT><<<128, 256, SEQ * LATENT * 4>>>(
        w_ih0, x, b_ih0, b_hh0, xg);
    for (int t = 0; t < SEQ; t++) {
        lstm_step_kernel<<<256, 128>>>(
            whh0h, xg + t * GATES,
            (t == 0) ? nullptr : (h1 + (t - 1) * HID),
            c, h1 + t * HID, nullptr, t == 0 ? 1 : 0);
    }

    // Layer 1
    gate_gemm_kernel<HID><<<128, 256, SEQ * HID * 4>>>(
        w_ih1, h1, b_ih1, b_hh1, xg);
    float* h2 = out + HID;
    for (int t = 0; t < SEQ; t++) {
        lstm_step_kernel<<<256, 128>>>(
            whh1h, xg + t * GATES,
            (t == 0) ? nullptr : (h2 + (t - 1) * HID),
            c, h2 + t * HID,
            (t == SEQ - 1) ? out : nullptr, t == 0 ? 1 : 0);
    }
}

// round 6
// speedup vs baseline: 1.2547x; 1.2547x over previous
#include <cuda_runtime.h>
#include <math.h>

#define NCTA   128
#define NTHR   256
#define NWRP   8
#define HID    1024
#define GATES  4096
#define LATENT 2048
#define SEQ    16
#define SMEM_BYTES (SEQ * LATENT * 4)   // 128KB -> 1 CTA/SM -> 128 CTAs co-resident

// ---------------- device scratch (no allocation allowed) ----------------
__device__ float    g_xg[SEQ * GATES];  // gate pre-activations, current layer
__device__ float    g_h1[SEQ * HID];    // layer-0 hidden outputs (per-step rows)
__device__ unsigned g_bar;              // flip-bit grid barrier state (zero-init,
                                        // wrap-safe, never reset -> replay-safe)

// ---------------- grid barrier: cooperative-groups flip-bit algorithm ----
__device__ __forceinline__ void grid_barrier() {
    __syncthreads();
    if (threadIdx.x == 0) {
        __threadfence();   // release: make this CTA's prior stores visible
        unsigned nb = (blockIdx.x == 0) ? (0x80000000u - (NCTA - 1u)) : 1u;
        unsigned old = atomicAdd(&g_bar, nb);
        while ((((old ^ *(volatile unsigned*)&g_bar)) & 0x80000000u) == 0u) { }
        __threadfence();   // acquire
    }
    __syncthreads();
}

__device__ __forceinline__ float sigmoidf_(float x) {
    return 1.0f / (1.0f + __expf(-x));
}

// L1-bypassing accessors for cross-CTA mutable data (L1 must never serve them)
__device__ __forceinline__ float4 ldcg4(const float4* p) {
    float4 v;
    asm volatile("ld.global.cg.v4.f32 {%0,%1,%2,%3}, [%4];"
                 : "=f"(v.x), "=f"(v.y), "=f"(v.z), "=f"(v.w) : "l"(p) : "memory");
    return v;
}
__device__ __forceinline__ float ldcg1(const float* p) {
    float v;
    asm volatile("ld.global.cg.f32 %0, [%1];" : "=f"(v) : "l"(p) : "memory");
    return v;
}
__device__ __forceinline__ void stcg1(float* p, float v) {
    asm volatile("st.global.cg.f32 [%0], %1;" :: "l"(p), "f"(v) : "memory");
}

// ---------------- input GEMM phase (R4-verbatim math) -----------------------
// out[t][row] = inp[t] . W[row] + b1[row] + b2[row]; warp gw owns rows 4gw..+3.
// inp staged to SMEM via ld.cg (fresh from L2), W streamed with plain loads.
template <int D>
__device__ void gate_gemm_dev(const float* __restrict__ W,
                              const float* __restrict__ inp,
                              const float* __restrict__ b1,
                              const float* __restrict__ b2,
                              float* __restrict__ out,
                              float* smem) {
    const int tid  = threadIdx.x;
    const int lane = tid & 31;
    const int warp = tid >> 5;
    const int NF4  = D / 4;

    const float4* in4 = (const float4*)inp;
    float4* s4 = (float4*)smem;
    for (int i = tid; i < SEQ * D / 4; i += NTHR) s4[i] = ldcg4(&in4[i]);
    __syncthreads();
    const float4* xs4 = (const float4*)smem;

    const int row = (blockIdx.x * NWRP + warp) * 4;   // 128*8 warps == GATES/4

    float acc[4][SEQ];
#pragma unroll
    for (int r = 0; r < 4; r++)
#pragma unroll
        for (int t = 0; t < SEQ; t++) acc[r][t] = 0.0f;

    const float4* w0 = (const float4*)(W + (size_t)(row + 0) * D);
    const float4* w1 = (const float4*)(W + (size_t)(row + 1) * D);
    const float4* w2 = (const float4*)(W + (size_t)(row + 2) * D);
    const float4* w3 = (const float4*)(W + (size_t)(row + 3) * D);

    for (int ci = lane; ci < NF4; ci += 32) {
        float4 a0 = w0[ci], a1 = w1[ci], a2 = w2[ci], a3 = w3[ci];
#pragma unroll
        for (int t = 0; t < SEQ; t++) {
            float4 xv = xs4[t * NF4 + ci];
            acc[0][t] += a0.x * xv.x + a0.y * xv.y + a0.z * xv.z + a0.w * xv.w;
            acc[1][t] += a1.x * xv.x + a1.y * xv.y + a1.z * xv.z + a1.w * xv.w;
            acc[2][t] += a2.x * xv.x + a2.y * xv.y + a2.z * xv.z + a2.w * xv.w;
            acc[3][t] += a3.x * xv.x + a3.y * xv.y + a3.z * xv.z + a3.w * xv.w;
        }
    }
#pragma unroll
    for (int r = 0; r < 4; r++) {
#pragma unroll
        for (int t = 0; t < SEQ; t++) {
            float s = acc[r][t];
#pragma unroll
            for (int off = 16; off; off >>= 1)
                s += __shfl_xor_sync(0xffffffffu, s, off);
            if (lane == 0)
                stcg1(&out[t * GATES + row + r], s + b1[row + r] + b2[row + r]);
        }
    }
}

// ---------------- one LSTM timestep (R4-verbatim math) ----------------------
// Warp gw = blockIdx*8+warp owns hidden unit j = gw. h_prev (distinct buffer
// written by the previous step, before the intervening grid barrier) is staged
// once per CTA to SMEM via ld.cg, then each warp computes the 4 gate dots with
// plain weight loads; lane 0 does the pointwise update; c lives in a register.
__device__ void lstm_step_dev(const float* __restrict__ whh,
                              const float* __restrict__ xg_t,
                              const float* __restrict__ h_prev,  // null iff t==0
                              float* creg,
                              float* __restrict__ h_out,
                              float* __restrict__ last_out,      // null unless last
                              float* smem, int j) {
    const int tid  = threadIdx.x;
    const int lane = tid & 31;

    float dot[4] = {0.f, 0.f, 0.f, 0.f};
    if (h_prev) {
        float4* hs4 = (float4*)smem;
        const float4* hp4 = (const float4*)h_prev;
        for (int i = tid; i < HID / 4; i += NTHR) hs4[i] = ldcg4(&hp4[i]);
        __syncthreads();

        float4 hv[8];
#pragma unroll
        for (int q = 0; q < 8; q++) hv[q] = hs4[lane + 32 * q];

#pragma unroll
        for (int g = 0; g < 4; g++) {
            const float4* wr = (const float4*)(whh + (size_t)(g * HID + j) * HID);
            float s = 0.0f;
#pragma unroll
            for (int q = 0; q < 8; q++) {
                float4 w = wr[lane + 32 * q];
                s += w.x * hv[q].x + w.y * hv[q].y + w.z * hv[q].z + w.w * hv[q].w;
            }
#pragma unroll
            for (int off = 16; off; off >>= 1)
                s += __shfl_xor_sync(0xffffffffu, s, off);
            dot[g] = s;
        }
    }

    if (lane == 0) {
        float gi = ldcg1(&xg_t[0 * HID + j]) + dot[0];
        float gf = ldcg1(&xg_t[1 * HID + j]) + dot[1];
        float gg = ldcg1(&xg_t[2 * HID + j]) + dot[2];
        float go = ldcg1(&xg_t[3 * HID + j]) + dot[3];
        float iv = sigmoidf_(gi);
        float fv = sigmoidf_(gf);
        float gv = tanhf(gg);
        float ov = sigmoidf_(go);
        float cn = fv * (*creg) + iv * gv;   // *creg == 0 at t==0
        *creg = cn;
        float hval = ov * tanhf(cn);
        stcg1(&h_out[j], hval);
        if (last_out) last_out[j] = hval;
    }
}

// ---------------- single persistent kernel ----------------------------------
__global__ void __launch_bounds__(NTHR, 1)
lstm2_persist(const float* __restrict__ x,
              const float* __restrict__ w_ih0, const float* __restrict__ w_hh0,
              const float* __restrict__ b_ih0, const float* __restrict__ b_hh0,
              const float* __restrict__ w_ih1, const float* __restrict__ w_hh1,
              const float* __restrict__ b_ih1, const float* __restrict__ b_hh1,
              float* __restrict__ out) {
    extern __shared__ float smem[];
    const int warp = threadIdx.x >> 5;
    const int j    = blockIdx.x * NWRP + warp;   // 128*8 == HID exactly

    // Phase A: xg = x @ w_ih0^T + b_ih0 + b_hh0
    gate_gemm_dev<LATENT>(w_ih0, x, b_ih0, b_hh0, g_xg, smem);
    grid_barrier();

    // Layer 0 recurrence (h rows in distinct per-step buffers -> no WAR)
    float c = 0.0f;
    for (int t = 0; t < SEQ; t++) {
        lstm_step_dev(w_hh0, g_xg + t * GATES,
                      t ? (g_h1 + (t - 1) * HID) : nullptr,
                      &c, g_h1 + t * HID, nullptr, smem, j);
        grid_barrier();
    }

    // Phase C: xg = h1 @ w_ih1^T + b_ih1 + b_hh1
    gate_gemm_dev<HID>(w_ih1, g_h1, b_ih1, b_hh1, g_xg, smem);
    grid_barrier();

    // Layer 1 recurrence -> out: [0:HID) last_output, [HID:) h2 rows
    c = 0.0f;
    float* h2 = out + HID;
    for (int t = 0; t < SEQ; t++) {
        lstm_step_dev(w_hh1, g_xg + t * GATES,
                      t ? (h2 + (t - 1) * HID) : nullptr,
                      &c, h2 + t * HID,
                      (t == SEQ - 1) ? out : nullptr, smem, j);
        grid_barrier();
    }
}

// ---------------- host launch (graph-capturable, single node) ---------------
extern "C" void kernel_launch(void* const* d_in, const int* in_sizes, int n_in,
                              void* d_out, int out_size) {
    const float* x     = (const float*)d_in[0];
    const float* w_ih0 = (const float*)d_in[1];
    const float* w_hh0 = (const float*)d_in[2];
    const float* b_ih0 = (const float*)d_in[3];
    const float* b_hh0 = (const float*)d_in[4];
    const float* w_ih1 = (const float*)d_in[5];
    const float* w_hh1 = (const float*)d_in[6];
    const float* b_ih1 = (const float*)d_in[7];
    const float* b_hh1 = (const float*)d_in[8];
    float* out = (float*)d_out;

    cudaFuncSetAttribute(lstm2_persist,
                         cudaFuncAttributeMaxDynamicSharedMemorySize, SMEM_BYTES);
    lstm2_persist<<<NCTA, NTHR, SMEM_BYTES>>>(x, w_ih0, w_hh0, b_ih0, b_hh0,
                                              w_ih1, w_hh1, b_ih1, b_hh1, out);
}